// round 14
// baseline (speedup 1.0000x reference)
#include <cuda_runtime.h>
#include <cuda_fp16.h>
#include <cstdint>
#include <cstddef>

// Problem constants
#define Bb 16
#define Ss 2048
#define Ee 1024

// ---------------- device scratch (static globals: allocation-free) ----------
__device__ __half g_xh [(size_t)Bb * Ss * Ee];          // 67 MB  x in fp16
__device__ __half g_Yh [(size_t)Bb * Ss * Ee];          // 67 MB  Y = x @ Mt^T
__device__ __half g_E  [(size_t)Bb * Ss * Ss];          // 134 MB exp(score-4)
__device__ float  g_Mt  [(size_t)Ee * Ee];              // 4 MB   Wk^T Wq (fp32)
__device__ __half g_Mth[(size_t)Ee * Ee];               // 2 MB
__device__ float  g_sv [Ee];                            // s = Wk^T bq
__device__ float  g_t3s[Bb * Ss];                       // (x . s)/32
__device__ float  g_r  [Bb * Ss];                       // row sums of E -> 1/r
__device__ float  g_w  [Bb * Ss];                       // softmax col means
__device__ float  g_u  [Bb * Ee];                       // weighted x

// =========================== PTX helpers (base compute_103) =================
__device__ __forceinline__ uint32_t smem_u32(const void* p) {
    uint32_t a;
    asm("{ .reg .u64 t; cvta.to.shared.u64 t, %1; cvt.u32.u64 %0, t; }"
        : "=r"(a) : "l"(p));
    return a;
}
#define CP_ASYNC16(d, s) \
    asm volatile("cp.async.cg.shared.global [%0], [%1], 16;" :: "r"(d), "l"(s))
#define CP_COMMIT() asm volatile("cp.async.commit_group;" ::: "memory")
#define CP_WAIT(n)  asm volatile("cp.async.wait_group %0;" :: "n"(n) : "memory")

// SW64 swizzle for 64-byte rows
#define SWZ64(o) ((o) ^ (((o) >> 3) & 0x30))

__device__ __forceinline__ void ldsm_x4(uint32_t* r, uint32_t addr) {
    asm volatile("ldmatrix.sync.aligned.m8n8.x4.shared.b16 {%0,%1,%2,%3}, [%4];"
                 : "=r"(r[0]), "=r"(r[1]), "=r"(r[2]), "=r"(r[3])
                 : "r"(addr));
}
__device__ __forceinline__ void mma16816(float* c, const uint32_t* a,
                                         const uint32_t* b) {
    asm volatile(
        "mma.sync.aligned.m16n8k16.row.col.f32.f16.f16.f32 "
        "{%0,%1,%2,%3}, {%4,%5,%6,%7}, {%8,%9}, {%0,%1,%2,%3};"
        : "+f"(c[0]), "+f"(c[1]), "+f"(c[2]), "+f"(c[3])
        : "r"(a[0]), "r"(a[1]), "r"(a[2]), "r"(a[3]), "r"(b[0]), "r"(b[1]));
}

// ======================= fp16 NT GEMM via mma.sync ==========================
// CTA tile 128x128x32; 4 warps (2x2), warp tile 64x64; 128 threads;
// __launch_bounds__(128,2) -> 2 CTAs/SM; NS=5 stages (deeper DRAM coverage).
// out_mode 1: Ch[m,n] = fp16( alpha * sum_k A[m,k]*B[n,k] )
// out_mode 2: v = alpha*acc + addv[col]; E = fp16(exp(v-4)); row sums -> rsum.
#define NS 5
#define STAGE 16384              // A 8 KB + B 8 KB
#define GEMM_DSMEM (NS * STAGE + 1024)

__global__ __launch_bounds__(128, 2) void gemm_f16(
    const __half* __restrict__ A, const __half* __restrict__ B,
    __half* __restrict__ C, const float* __restrict__ addv,
    float* __restrict__ rsum,
    int M, int N, int K, float alpha,
    long long sA, long long sB, long long sC, long long sAdd, int out_mode)
{
    extern __shared__ char dynsm[];
    const uint32_t sbase = (smem_u32(dynsm) + 1023u) & ~1023u;

    const int tid  = threadIdx.x;
    const int lane = tid & 31;
    const int wid  = tid >> 5;       // 0..3
    const int wm   = wid >> 1;       // 0..1 -> 64-row band
    const int wn   = wid & 1;        // 0..1 -> 64-col band
    const int NC   = K / 32;

    const size_t arow0 = (size_t)blockIdx.z * sA + (size_t)(blockIdx.y * 128) * K;
    const size_t brow0 = (size_t)blockIdx.z * sB + (size_t)(blockIdx.x * 128) * K;

    auto load_stage = [&](int c) {
        const uint32_t st = sbase + (uint32_t)(c % NS) * STAGE;
        const int kc0 = c * 32;
#pragma unroll
        for (int t = 0; t < 2; t++) {
            const __half* src = t ? B : A;
            const size_t  bs  = t ? brow0 : arow0;
            const uint32_t tb = st + (uint32_t)t * 8192;
#pragma unroll
            for (int i = 0; i < 4; i++) {
                const int idx = tid + 128 * i;      // 0..511
                const int row = idx >> 2;
                const int ch  = idx & 3;
                const __half* g = src + bs + (size_t)row * K + kc0 + ch * 8;
                CP_ASYNC16(tb + SWZ64((uint32_t)(row * 64 + ch * 16)), g);
            }
        }
        CP_COMMIT();
    };

    float acc[4][8][4];
#pragma unroll
    for (int i = 0; i < 4; i++)
#pragma unroll
        for (int j = 0; j < 8; j++)
#pragma unroll
            for (int r = 0; r < 4; r++) acc[i][j][r] = 0.0f;

    load_stage(0);
    load_stage(1);
    load_stage(2);
    load_stage(3);

    const int a_r = wm * 64 + (lane & 7) + ((lane >> 3) & 1) * 8;  // + mi*16
    const int a_c = (lane >> 4) & 1;                               // + ks*2
    const int b_r = wn * 64 + (lane & 7) + ((lane >> 4) & 1) * 8;  // + p*16
    const int b_c = (lane >> 3) & 1;                               // + ks*2

    for (int c = 0; c < NC; c++) {
        CP_WAIT(3);
        __syncthreads();
        if (c + 4 < NC) load_stage(c + 4); else CP_COMMIT();  // keep group count

        const uint32_t st = sbase + (uint32_t)(c % NS) * STAGE;
#pragma unroll
        for (int ks = 0; ks < 2; ks++) {
            uint32_t ah[4][4], bh[8][2];
#pragma unroll
            for (int mi = 0; mi < 4; mi++) {
                const uint32_t off =
                    SWZ64((uint32_t)((a_r + mi * 16) * 64 + (a_c + ks * 2) * 16));
                ldsm_x4(ah[mi], st + off);
            }
#pragma unroll
            for (int p = 0; p < 4; p++) {
                const uint32_t off =
                    SWZ64((uint32_t)((b_r + p * 16) * 64 + (b_c + ks * 2) * 16));
                uint32_t t0[4];
                ldsm_x4(t0, st + 8192 + off);
                bh[2 * p][0] = t0[0]; bh[2 * p][1] = t0[1];
                bh[2 * p + 1][0] = t0[2]; bh[2 * p + 1][1] = t0[3];
            }
#pragma unroll
            for (int mi = 0; mi < 4; mi++)
#pragma unroll
                for (int ni = 0; ni < 8; ni++)
                    mma16816(acc[mi][ni], ah[mi], bh[ni]);
        }
    }

    // ------------------------------ epilogue --------------------------------
    const int gr0 = blockIdx.y * 128 + wm * 64 + (lane >> 2);
    const int gc0 = blockIdx.x * 128 + wn * 64 + 2 * (lane & 3);
    const size_t cb = (size_t)blockIdx.z * sC;

    if (out_mode == 1) {
#pragma unroll
        for (int mi = 0; mi < 4; mi++)
#pragma unroll
            for (int ni = 0; ni < 8; ni++) {
                const int row = gr0 + mi * 16;
                const int col = gc0 + ni * 8;
                *(__half2*)&C[cb + (size_t)row * N + col] =
                    __floats2half2_rn(acc[mi][ni][0] * alpha,
                                      acc[mi][ni][1] * alpha);
                *(__half2*)&C[cb + (size_t)(row + 8) * N + col] =
                    __floats2half2_rn(acc[mi][ni][2] * alpha,
                                      acc[mi][ni][3] * alpha);
            }
    } else {
        // hoisted addv loads: a0/a1 depend only on ni
        float av0[8], av1[8];
        {
            const float* av = addv + (size_t)blockIdx.z * sAdd;
#pragma unroll
            for (int ni = 0; ni < 8; ni++) {
                av0[ni] = __ldg(&av[gc0 + ni * 8]);
                av1[ni] = __ldg(&av[gc0 + ni * 8 + 1]);
            }
        }
        float* rb = rsum + (size_t)blockIdx.z * Ss;
#pragma unroll
        for (int mi = 0; mi < 4; mi++) {
            float s_lo = 0.0f, s_hi = 0.0f;
            const int row = gr0 + mi * 16;
#pragma unroll
            for (int ni = 0; ni < 8; ni++) {
                const int col = gc0 + ni * 8;
                const float e0 = __expf(acc[mi][ni][0] * alpha + av0[ni] - 4.0f);
                const float e1 = __expf(acc[mi][ni][1] * alpha + av1[ni] - 4.0f);
                const float e2 = __expf(acc[mi][ni][2] * alpha + av0[ni] - 4.0f);
                const float e3 = __expf(acc[mi][ni][3] * alpha + av1[ni] - 4.0f);
                s_lo += e0 + e1;
                s_hi += e2 + e3;
                *(__half2*)&C[cb + (size_t)row * N + col] =
                    __floats2half2_rn(e0, e1);
                *(__half2*)&C[cb + (size_t)(row + 8) * N + col] =
                    __floats2half2_rn(e2, e3);
            }
            s_lo += __shfl_xor_sync(0xFFFFFFFFu, s_lo, 1);
            s_lo += __shfl_xor_sync(0xFFFFFFFFu, s_lo, 2);
            s_hi += __shfl_xor_sync(0xFFFFFFFFu, s_hi, 1);
            s_hi += __shfl_xor_sync(0xFFFFFFFFu, s_hi, 2);
            if ((lane & 3) == 0) {
                atomicAdd(&rb[row], s_lo);
                atomicAdd(&rb[row + 8], s_hi);
            }
        }
    }
}

// ============= TN fp32 sgemm split-K: Mt[m,n] += sum_g A[g,m]*B[g,n] ========
// MT_SPLITK=8 (measured best).
#define MT_SPLITK 8
__global__ __launch_bounds__(256) void sgemm_tn_splitk(
    const float* __restrict__ A, const float* __restrict__ B,
    float* __restrict__ C, int M, int N, int K)
{
    __shared__ float As[8][128];
    __shared__ float Bs[8][128];
    const int tid  = threadIdx.x;
    const int trow = tid >> 4, tcol = tid & 15;
    const int krow = tid >> 5, col4 = (tid & 31) * 4;
    const int m0 = blockIdx.y * 128, n0 = blockIdx.x * 128;
    const int kslice = K / MT_SPLITK;
    const int kbeg = blockIdx.z * kslice, kend = kbeg + kslice;

    float acc[8][8];
#pragma unroll
    for (int i = 0; i < 8; i++)
#pragma unroll
        for (int j = 0; j < 8; j++) acc[i][j] = 0.0f;

    for (int k0 = kbeg; k0 < kend; k0 += 8) {
        const float4 a4 = *(const float4*)&A[(size_t)(k0 + krow) * M + m0 + col4];
        const float4 b4 = *(const float4*)&B[(size_t)(k0 + krow) * N + n0 + col4];
        __syncthreads();
        *(float4*)&As[krow][col4] = a4;
        *(float4*)&Bs[krow][col4] = b4;
        __syncthreads();
#pragma unroll
        for (int kk = 0; kk < 8; kk++) {
            float ra[8], rb[8];
#pragma unroll
            for (int i = 0; i < 8; i++) ra[i] = As[kk][trow * 8 + i];
#pragma unroll
            for (int j = 0; j < 8; j++) rb[j] = Bs[kk][tcol * 8 + j];
#pragma unroll
            for (int i = 0; i < 8; i++)
#pragma unroll
                for (int j = 0; j < 8; j++) acc[i][j] += ra[i] * rb[j];
        }
    }
#pragma unroll
    for (int i = 0; i < 8; i++)
#pragma unroll
        for (int j = 0; j < 8; j++)
            atomicAdd(&C[(size_t)(m0 + trow * 8 + i) * N + n0 + tcol * 8 + j],
                      acc[i][j]);
}

// =============== x -> fp16 conversion fused with accumulator zeroing ========
__global__ __launch_bounds__(256) void cvt_x_and_zero(
    const float* __restrict__ in, __half* __restrict__ out, int n4,
    float* __restrict__ Mt, float* __restrict__ sv,
    float* __restrict__ r, float* __restrict__ w, float* __restrict__ u)
{
    const int idx = blockIdx.x * 256 + threadIdx.x;
    if (idx < n4) {
        const float4 v = ((const float4*)in)[idx];
        ((__half2*)out)[idx * 2 + 0] = __floats2half2_rn(v.x, v.y);
        ((__half2*)out)[idx * 2 + 1] = __floats2half2_rn(v.z, v.w);
    }
    if (idx < Ee * Ee) Mt[idx] = 0.0f;
    if (idx < Ee)      sv[idx] = 0.0f;
    if (idx < Bb * Ss) { r[idx] = 0.0f; w[idx] = 0.0f; }
    if (idx < Bb * Ee) u[idx] = 0.0f;
}

__global__ __launch_bounds__(256) void cvt_f32_f16(
    const float* __restrict__ in, __half* __restrict__ out, int n4)
{
    const int idx = blockIdx.x * 256 + threadIdx.x;
    if (idx >= n4) return;
    const float4 v = ((const float4*)in)[idx];
    ((__half2*)out)[idx * 2 + 0] = __floats2half2_rn(v.x, v.y);
    ((__half2*)out)[idx * 2 + 1] = __floats2half2_rn(v.z, v.w);
}

// s[f] += sum_{e in chunk} Wk[e,f]*bq[e]   grid (Ee/256, ECH); ECH=64 measured.
#define ECH 64
__global__ __launch_bounds__(256) void calc_s(
    const float* __restrict__ Wk, const float* __restrict__ bq,
    float* __restrict__ s)
{
    const int f  = blockIdx.x * 256 + threadIdx.x;
    const int e0 = blockIdx.y * (Ee / ECH);
    float acc = 0.0f;
#pragma unroll 4
    for (int e = e0; e < e0 + Ee / ECH; e++)
        acc += Wk[(size_t)e * Ee + f] * __ldg(&bq[e]);
    atomicAdd(&s[f], acc);
}

// t3s[r] = (xh[r,:] . s) / 32   (warp per row)
__global__ __launch_bounds__(256) void t3_kernel(
    const __half* __restrict__ xh, const float* __restrict__ s,
    float* __restrict__ t3s)
{
    const int warp = threadIdx.x >> 5, lane = threadIdx.x & 31;
    const int row = blockIdx.x * 8 + warp;
    const __half2* xr = (const __half2*)(xh + (size_t)row * Ee);
    float acc = 0.0f;
    for (int e2 = lane; e2 < Ee / 2; e2 += 32) {
        const float2 v = __half22float2(xr[e2]);
        acc += v.x * __ldg(&s[2 * e2]) + v.y * __ldg(&s[2 * e2 + 1]);
    }
#pragma unroll
    for (int o = 16; o > 0; o >>= 1) acc += __shfl_down_sync(0xFFFFFFFFu, acc, o);
    if (lane == 0) t3s[row] = acc * (1.0f / 32.0f);
}

__global__ void inv_r(float* __restrict__ r, int n)
{
    const int i = blockIdx.x * 256 + threadIdx.x;
    if (i < n) r[i] = 1.0f / r[i];
}

// w[b,2k..2k+1] += (1/S) * sum_{q in chunk} E[b,q,2k..2k+1] * ri[b,q]
#define QCH 16
__global__ __launch_bounds__(256) void col_mean(const __half* __restrict__ E,
                                                const float* __restrict__ ri,
                                                float* __restrict__ w)
{
    const int b  = blockIdx.y;
    const int k2 = blockIdx.x * 256 + threadIdx.x;   // half2 index
    const int q0 = blockIdx.z * (Ss / QCH);
    const __half2* base = (const __half2*)(E + (size_t)b * Ss * Ss) + k2;
    const float* rb = ri + b * Ss;
    float ax = 0.0f, ay = 0.0f;
#pragma unroll 4
    for (int q = q0; q < q0 + Ss / QCH; q++) {
        const float2 e = __half22float2(base[(size_t)q * (Ss / 2)]);
        const float rv = __ldg(&rb[q]);
        ax += e.x * rv;
        ay += e.y * rv;
    }
    atomicAdd(&w[b * Ss + 2 * k2],     ax * (1.0f / Ss));
    atomicAdd(&w[b * Ss + 2 * k2 + 1], ay * (1.0f / Ss));
}

// u[b,f] += sum_{k in chunk} w[b,k] * x[b,k,f]   (fp32 x for accuracy)
#define KCH 16
__global__ __launch_bounds__(256) void weighted_x(const float* __restrict__ x,
                                                  const float* __restrict__ w,
                                                  float* __restrict__ u)
{
    const int b  = blockIdx.y;
    const int f  = blockIdx.x * 256 + threadIdx.x;
    const int k0 = blockIdx.z * (Ss / KCH);
    const float* xb = x + (size_t)b * Ss * Ee + (size_t)k0 * Ee + f;
    const float* wb = w + b * Ss + k0;
    float acc = 0.0f;
#pragma unroll 4
    for (int k = 0; k < Ss / KCH; k++)
        acc += __ldg(&wb[k]) * xb[(size_t)k * Ee];
    atomicAdd(&u[b * Ee + f], acc);
}

__global__ __launch_bounds__(256) void out_gemm(const float* __restrict__ u,
                                                const float* __restrict__ wv,
                                                const float* __restrict__ bv,
                                                float* __restrict__ out)
{
    const int warp = threadIdx.x >> 5, lane = threadIdx.x & 31;
    const int e = blockIdx.x * 8 + warp;
    const int b = blockIdx.y;
    const float* ub = u + b * Ee;
    const float* wr = wv + (size_t)e * Ee;
    float acc = 0.0f;
    for (int f = lane; f < Ee; f += 32) acc += ub[f] * wr[f];
#pragma unroll
    for (int o = 16; o > 0; o >>= 1) acc += __shfl_down_sync(0xFFFFFFFFu, acc, o);
    if (lane == 0) out[b * Ee + e] = acc + __ldg(&bv[e]);
}

// ---------------------------------------------------------------------------
extern "C" void kernel_launch(void* const* d_in, const int* in_sizes, int n_in,
                              void* d_out, int out_size)
{
    const float* x  = (const float*)d_in[0];
    const float* wq = (const float*)d_in[1];
    const float* bq = (const float*)d_in[2];
    const float* wk = (const float*)d_in[3];
    const float* bk = (const float*)d_in[4];
    const float* wv = (const float*)d_in[5];
    const float* bv = (const float*)d_in[6];
    float* out = (float*)d_out;
    (void)bk;  // constant along k -> cancels in softmax

    __half *xh, *Yh, *E, *Mth;
    float *Mt, *sv, *t3s, *r, *w, *u;
    cudaGetSymbolAddress((void**)&xh,  g_xh);
    cudaGetSymbolAddress((void**)&Yh,  g_Yh);
    cudaGetSymbolAddress((void**)&E,   g_E);
    cudaGetSymbolAddress((void**)&Mt,  g_Mt);
    cudaGetSymbolAddress((void**)&Mth, g_Mth);
    cudaGetSymbolAddress((void**)&sv,  g_sv);
    cudaGetSymbolAddress((void**)&t3s, g_t3s);
    cudaGetSymbolAddress((void**)&r,   g_r);
    cudaGetSymbolAddress((void**)&w,   g_w);
    cudaGetSymbolAddress((void**)&u,   g_u);

    cudaFuncSetAttribute(gemm_f16,
                         cudaFuncAttributeMaxDynamicSharedMemorySize, GEMM_DSMEM);

    const long long SE  = (long long)Ss * Ee;
    const long long SS2 = (long long)Ss * Ss;

    // 1) x -> fp16, fused with zeroing of all accumulators (Mt, sv, r, w, u)
    cvt_x_and_zero<<<(Bb * Ss * Ee / 4 + 255) / 256, 256>>>(
        x, xh, Bb * Ss * Ee / 4, Mt, sv, r, w, u);

    // 2) Mt[f,e] = sum_g Wk[g,f] Wq[g,e]  (split-K 8, atomic), then -> fp16
    {
        dim3 grid(Ee / 128, Ee / 128, MT_SPLITK);
        sgemm_tn_splitk<<<grid, 256>>>(wk, wq, Mt, Ee, Ee, Ee);
    }
    cvt_f32_f16<<<(Ee * Ee / 4 + 255) / 256, 256>>>(Mt, Mth, Ee * Ee / 4);

    // 3) s = Wk^T bq (ECH=64) ; t3s = (xh . s)/32
    {
        dim3 grid(Ee / 256, ECH);
        calc_s<<<grid, 256>>>(wk, bq, sv);
    }
    t3_kernel<<<Bb * Ss / 8, 256>>>(xh, sv, t3s);

    // 4) GEMM1: Yh = xh @ Mth^T   (M=B*S, N=E, K=E)
    {
        dim3 grid(Ee / 128, (Bb * Ss) / 128, 1);
        gemm_f16<<<grid, 128, GEMM_DSMEM>>>(
            xh, Mth, Yh, nullptr, nullptr,
            Bb * Ss, Ee, Ee, 1.0f, 0, 0, 0, 0, 1);
    }

    // 5) GEMM2 + fused softmax-numerator: E[b,q,k] = exp(score-4), r[b,q] = row sums
    {
        dim3 grid(Ss / 128, Ss / 128, Bb);
        gemm_f16<<<grid, 128, GEMM_DSMEM>>>(
            Yh, xh, E, t3s, r,
            Ss, Ss, Ee, 1.0f / 32.0f, SE, SE, SS2, Ss, 2);
    }

    // 6) r -> 1/r ; column means (half2, QCH=16) ; weighted x ; final projection
    inv_r<<<(Bb * Ss + 255) / 256, 256>>>(r, Bb * Ss);
    {
        dim3 grid(Ss / 512, Bb, QCH);
        col_mean<<<grid, 256>>>(E, r, w);
    }
    {
        dim3 grid(Ee / 256, Bb, KCH);
        weighted_x<<<grid, 256>>>(x, w, u);
    }
    {
        dim3 grid(Ee / 8, Bb);
        out_gemm<<<grid, 256>>>(u, wv, bv, out);
    }
}

// round 15
// speedup vs baseline: 1.1625x; 1.1625x over previous
#include <cuda_runtime.h>
#include <cuda_fp16.h>
#include <cstdint>
#include <cstddef>

// Problem constants
#define Bb 16
#define Ss 2048
#define Ee 1024

// ---------------- device scratch (static globals: allocation-free) ----------
__device__ __half g_xh [(size_t)Bb * Ss * Ee];          // 67 MB  x in fp16
__device__ __half g_Yh [(size_t)Bb * Ss * Ee];          // 67 MB  Y = x @ Mt^T
__device__ __half g_E  [(size_t)Bb * Ss * Ss];          // 134 MB exp(score-4)
__device__ float  g_Mt  [(size_t)Ee * Ee];              // 4 MB   Wk^T Wq (fp32)
__device__ __half g_Mth[(size_t)Ee * Ee];               // 2 MB
__device__ float  g_sv [Ee];                            // s = Wk^T bq
__device__ float  g_t3s[Bb * Ss];                       // (x . s)/32
__device__ float  g_r  [Bb * Ss];                       // row sums of E -> 1/r
__device__ float  g_w  [Bb * Ss];                       // softmax col means
__device__ float  g_u  [Bb * Ee];                       // weighted x

// =========================== PTX helpers (base compute_103) =================
__device__ __forceinline__ uint32_t smem_u32(const void* p) {
    uint32_t a;
    asm("{ .reg .u64 t; cvta.to.shared.u64 t, %1; cvt.u32.u64 %0, t; }"
        : "=r"(a) : "l"(p));
    return a;
}
#define CP_ASYNC16(d, s) \
    asm volatile("cp.async.cg.shared.global [%0], [%1], 16;" :: "r"(d), "l"(s))
#define CP_COMMIT() asm volatile("cp.async.commit_group;" ::: "memory")
#define CP_WAIT(n)  asm volatile("cp.async.wait_group %0;" :: "n"(n) : "memory")

// SW64 swizzle for 64-byte rows
#define SWZ64(o) ((o) ^ (((o) >> 3) & 0x30))

__device__ __forceinline__ void ldsm_x4(uint32_t* r, uint32_t addr) {
    asm volatile("ldmatrix.sync.aligned.m8n8.x4.shared.b16 {%0,%1,%2,%3}, [%4];"
                 : "=r"(r[0]), "=r"(r[1]), "=r"(r[2]), "=r"(r[3])
                 : "r"(addr));
}
__device__ __forceinline__ void mma16816(float* c, const uint32_t* a,
                                         const uint32_t* b) {
    asm volatile(
        "mma.sync.aligned.m16n8k16.row.col.f32.f16.f16.f32 "
        "{%0,%1,%2,%3}, {%4,%5,%6,%7}, {%8,%9}, {%0,%1,%2,%3};"
        : "+f"(c[0]), "+f"(c[1]), "+f"(c[2]), "+f"(c[3])
        : "r"(a[0]), "r"(a[1]), "r"(a[2]), "r"(a[3]), "r"(b[0]), "r"(b[1]));
}

// ======================= fp16 NT GEMM via mma.sync ==========================
// Measured-best config (round 13, 714.8us): CTA tile 128x128x32; 4 warps
// (2x2), warp tile 64x64; 128 threads; __launch_bounds__(128,2) -> 2 CTAs/SM;
// NS=4 stages (65 KB — NS=5's 81 KB broke 2-CTA residency, round 14).
// out_mode 1: Ch[m,n] = fp16( alpha * sum_k A[m,k]*B[n,k] )
// out_mode 2: v = alpha*acc + addv[col]; E = fp16(exp(v-4)); row sums -> rsum.
#define NS 4
#define STAGE 16384              // A 8 KB + B 8 KB
#define GEMM_DSMEM (NS * STAGE + 1024)

__global__ __launch_bounds__(128, 2) void gemm_f16(
    const __half* __restrict__ A, const __half* __restrict__ B,
    __half* __restrict__ C, const float* __restrict__ addv,
    float* __restrict__ rsum,
    int M, int N, int K, float alpha,
    long long sA, long long sB, long long sC, long long sAdd, int out_mode)
{
    extern __shared__ char dynsm[];
    const uint32_t sbase = (smem_u32(dynsm) + 1023u) & ~1023u;

    const int tid  = threadIdx.x;
    const int lane = tid & 31;
    const int wid  = tid >> 5;       // 0..3
    const int wm   = wid >> 1;       // 0..1 -> 64-row band
    const int wn   = wid & 1;        // 0..1 -> 64-col band
    const int NC   = K / 32;

    const size_t arow0 = (size_t)blockIdx.z * sA + (size_t)(blockIdx.y * 128) * K;
    const size_t brow0 = (size_t)blockIdx.z * sB + (size_t)(blockIdx.x * 128) * K;

    auto load_stage = [&](int c) {
        const uint32_t st = sbase + (uint32_t)(c % NS) * STAGE;
        const int kc0 = c * 32;
#pragma unroll
        for (int t = 0; t < 2; t++) {
            const __half* src = t ? B : A;
            const size_t  bs  = t ? brow0 : arow0;
            const uint32_t tb = st + (uint32_t)t * 8192;
#pragma unroll
            for (int i = 0; i < 4; i++) {
                const int idx = tid + 128 * i;      // 0..511
                const int row = idx >> 2;
                const int ch  = idx & 3;
                const __half* g = src + bs + (size_t)row * K + kc0 + ch * 8;
                CP_ASYNC16(tb + SWZ64((uint32_t)(row * 64 + ch * 16)), g);
            }
        }
        CP_COMMIT();
    };

    float acc[4][8][4];
#pragma unroll
    for (int i = 0; i < 4; i++)
#pragma unroll
        for (int j = 0; j < 8; j++)
#pragma unroll
            for (int r = 0; r < 4; r++) acc[i][j][r] = 0.0f;

    load_stage(0);
    load_stage(1);
    load_stage(2);

    const int a_r = wm * 64 + (lane & 7) + ((lane >> 3) & 1) * 8;  // + mi*16
    const int a_c = (lane >> 4) & 1;                               // + ks*2
    const int b_r = wn * 64 + (lane & 7) + ((lane >> 4) & 1) * 8;  // + p*16
    const int b_c = (lane >> 3) & 1;                               // + ks*2

    for (int c = 0; c < NC; c++) {
        CP_WAIT(2);
        __syncthreads();
        if (c + 3 < NC) load_stage(c + 3); else CP_COMMIT();  // keep group count

        const uint32_t st = sbase + (uint32_t)(c % NS) * STAGE;
#pragma unroll
        for (int ks = 0; ks < 2; ks++) {
            uint32_t ah[4][4], bh[8][2];
#pragma unroll
            for (int mi = 0; mi < 4; mi++) {
                const uint32_t off =
                    SWZ64((uint32_t)((a_r + mi * 16) * 64 + (a_c + ks * 2) * 16));
                ldsm_x4(ah[mi], st + off);
            }
#pragma unroll
            for (int p = 0; p < 4; p++) {
                const uint32_t off =
                    SWZ64((uint32_t)((b_r + p * 16) * 64 + (b_c + ks * 2) * 16));
                uint32_t t0[4];
                ldsm_x4(t0, st + 8192 + off);
                bh[2 * p][0] = t0[0]; bh[2 * p][1] = t0[1];
                bh[2 * p + 1][0] = t0[2]; bh[2 * p + 1][1] = t0[3];
            }
#pragma unroll
            for (int mi = 0; mi < 4; mi++)
#pragma unroll
                for (int ni = 0; ni < 8; ni++)
                    mma16816(acc[mi][ni], ah[mi], bh[ni]);
        }
    }

    // ------------------------------ epilogue --------------------------------
    const int gr0 = blockIdx.y * 128 + wm * 64 + (lane >> 2);
    const int gc0 = blockIdx.x * 128 + wn * 64 + 2 * (lane & 3);
    const size_t cb = (size_t)blockIdx.z * sC;

    if (out_mode == 1) {
#pragma unroll
        for (int mi = 0; mi < 4; mi++)
#pragma unroll
            for (int ni = 0; ni < 8; ni++) {
                const int row = gr0 + mi * 16;
                const int col = gc0 + ni * 8;
                *(__half2*)&C[cb + (size_t)row * N + col] =
                    __floats2half2_rn(acc[mi][ni][0] * alpha,
                                      acc[mi][ni][1] * alpha);
                *(__half2*)&C[cb + (size_t)(row + 8) * N + col] =
                    __floats2half2_rn(acc[mi][ni][2] * alpha,
                                      acc[mi][ni][3] * alpha);
            }
    } else {
        const float* av = addv + (size_t)blockIdx.z * sAdd;
        float* rb = rsum + (size_t)blockIdx.z * Ss;
#pragma unroll
        for (int mi = 0; mi < 4; mi++) {
            float s_lo = 0.0f, s_hi = 0.0f;
            const int row = gr0 + mi * 16;
#pragma unroll
            for (int ni = 0; ni < 8; ni++) {
                const int col = gc0 + ni * 8;
                const float a0 = __ldg(&av[col]);
                const float a1 = __ldg(&av[col + 1]);
                const float e0 = __expf(acc[mi][ni][0] * alpha + a0 - 4.0f);
                const float e1 = __expf(acc[mi][ni][1] * alpha + a1 - 4.0f);
                const float e2 = __expf(acc[mi][ni][2] * alpha + a0 - 4.0f);
                const float e3 = __expf(acc[mi][ni][3] * alpha + a1 - 4.0f);
                s_lo += e0 + e1;
                s_hi += e2 + e3;
                *(__half2*)&C[cb + (size_t)row * N + col] =
                    __floats2half2_rn(e0, e1);
                *(__half2*)&C[cb + (size_t)(row + 8) * N + col] =
                    __floats2half2_rn(e2, e3);
            }
            s_lo += __shfl_xor_sync(0xFFFFFFFFu, s_lo, 1);
            s_lo += __shfl_xor_sync(0xFFFFFFFFu, s_lo, 2);
            s_hi += __shfl_xor_sync(0xFFFFFFFFu, s_hi, 1);
            s_hi += __shfl_xor_sync(0xFFFFFFFFu, s_hi, 2);
            if ((lane & 3) == 0) {
                atomicAdd(&rb[row], s_lo);
                atomicAdd(&rb[row + 8], s_hi);
            }
        }
    }
}

// ============= TN fp32 sgemm split-K: Mt[m,n] += sum_g A[g,m]*B[g,n] ========
// MT_SPLITK=8 (round-11/13 measured best).
#define MT_SPLITK 8
__global__ __launch_bounds__(256) void sgemm_tn_splitk(
    const float* __restrict__ A, const float* __restrict__ B,
    float* __restrict__ C, int M, int N, int K)
{
    __shared__ float As[8][128];
    __shared__ float Bs[8][128];
    const int tid  = threadIdx.x;
    const int trow = tid >> 4, tcol = tid & 15;
    const int krow = tid >> 5, col4 = (tid & 31) * 4;
    const int m0 = blockIdx.y * 128, n0 = blockIdx.x * 128;
    const int kslice = K / MT_SPLITK;
    const int kbeg = blockIdx.z * kslice, kend = kbeg + kslice;

    float acc[8][8];
#pragma unroll
    for (int i = 0; i < 8; i++)
#pragma unroll
        for (int j = 0; j < 8; j++) acc[i][j] = 0.0f;

    for (int k0 = kbeg; k0 < kend; k0 += 8) {
        const float4 a4 = *(const float4*)&A[(size_t)(k0 + krow) * M + m0 + col4];
        const float4 b4 = *(const float4*)&B[(size_t)(k0 + krow) * N + n0 + col4];
        __syncthreads();
        *(float4*)&As[krow][col4] = a4;
        *(float4*)&Bs[krow][col4] = b4;
        __syncthreads();
#pragma unroll
        for (int kk = 0; kk < 8; kk++) {
            float ra[8], rb[8];
#pragma unroll
            for (int i = 0; i < 8; i++) ra[i] = As[kk][trow * 8 + i];
#pragma unroll
            for (int j = 0; j < 8; j++) rb[j] = Bs[kk][tcol * 8 + j];
#pragma unroll
            for (int i = 0; i < 8; i++)
#pragma unroll
                for (int j = 0; j < 8; j++) acc[i][j] += ra[i] * rb[j];
        }
    }
#pragma unroll
    for (int i = 0; i < 8; i++)
#pragma unroll
        for (int j = 0; j < 8; j++)
            atomicAdd(&C[(size_t)(m0 + trow * 8 + i) * N + n0 + tcol * 8 + j],
                      acc[i][j]);
}

// =============== x -> fp16 conversion fused with accumulator zeroing ========
__global__ __launch_bounds__(256) void cvt_x_and_zero(
    const float* __restrict__ in, __half* __restrict__ out, int n4,
    float* __restrict__ Mt, float* __restrict__ sv,
    float* __restrict__ r, float* __restrict__ w, float* __restrict__ u)
{
    const int idx = blockIdx.x * 256 + threadIdx.x;
    if (idx < n4) {
        const float4 v = ((const float4*)in)[idx];
        ((__half2*)out)[idx * 2 + 0] = __floats2half2_rn(v.x, v.y);
        ((__half2*)out)[idx * 2 + 1] = __floats2half2_rn(v.z, v.w);
    }
    if (idx < Ee * Ee) Mt[idx] = 0.0f;
    if (idx < Ee)      sv[idx] = 0.0f;
    if (idx < Bb * Ss) { r[idx] = 0.0f; w[idx] = 0.0f; }
    if (idx < Bb * Ee) u[idx] = 0.0f;
}

__global__ __launch_bounds__(256) void cvt_f32_f16(
    const float* __restrict__ in, __half* __restrict__ out, int n4)
{
    const int idx = blockIdx.x * 256 + threadIdx.x;
    if (idx >= n4) return;
    const float4 v = ((const float4*)in)[idx];
    ((__half2*)out)[idx * 2 + 0] = __floats2half2_rn(v.x, v.y);
    ((__half2*)out)[idx * 2 + 1] = __floats2half2_rn(v.z, v.w);
}

// s[f] += sum_{e in chunk} Wk[e,f]*bq[e]   grid (Ee/256, ECH); ECH=64 measured.
#define ECH 64
__global__ __launch_bounds__(256) void calc_s(
    const float* __restrict__ Wk, const float* __restrict__ bq,
    float* __restrict__ s)
{
    const int f  = blockIdx.x * 256 + threadIdx.x;
    const int e0 = blockIdx.y * (Ee / ECH);
    float acc = 0.0f;
#pragma unroll 4
    for (int e = e0; e < e0 + Ee / ECH; e++)
        acc += Wk[(size_t)e * Ee + f] * __ldg(&bq[e]);
    atomicAdd(&s[f], acc);
}

// t3s[r] = (xh[r,:] . s) / 32   (warp per row)
__global__ __launch_bounds__(256) void t3_kernel(
    const __half* __restrict__ xh, const float* __restrict__ s,
    float* __restrict__ t3s)
{
    const int warp = threadIdx.x >> 5, lane = threadIdx.x & 31;
    const int row = blockIdx.x * 8 + warp;
    const __half2* xr = (const __half2*)(xh + (size_t)row * Ee);
    float acc = 0.0f;
    for (int e2 = lane; e2 < Ee / 2; e2 += 32) {
        const float2 v = __half22float2(xr[e2]);
        acc += v.x * __ldg(&s[2 * e2]) + v.y * __ldg(&s[2 * e2 + 1]);
    }
#pragma unroll
    for (int o = 16; o > 0; o >>= 1) acc += __shfl_down_sync(0xFFFFFFFFu, acc, o);
    if (lane == 0) t3s[row] = acc * (1.0f / 32.0f);
}

__global__ void inv_r(float* __restrict__ r, int n)
{
    const int i = blockIdx.x * 256 + threadIdx.x;
    if (i < n) r[i] = 1.0f / r[i];
}

// w[b,2k..2k+1] += (1/S) * sum_{q in chunk} E[b,q,2k..2k+1] * ri[b,q]
#define QCH 16
__global__ __launch_bounds__(256) void col_mean(const __half* __restrict__ E,
                                                const float* __restrict__ ri,
                                                float* __restrict__ w)
{
    const int b  = blockIdx.y;
    const int k2 = blockIdx.x * 256 + threadIdx.x;   // half2 index
    const int q0 = blockIdx.z * (Ss / QCH);
    const __half2* base = (const __half2*)(E + (size_t)b * Ss * Ss) + k2;
    const float* rb = ri + b * Ss;
    float ax = 0.0f, ay = 0.0f;
#pragma unroll 4
    for (int q = q0; q < q0 + Ss / QCH; q++) {
        const float2 e = __half22float2(base[(size_t)q * (Ss / 2)]);
        const float rv = __ldg(&rb[q]);
        ax += e.x * rv;
        ay += e.y * rv;
    }
    atomicAdd(&w[b * Ss + 2 * k2],     ax * (1.0f / Ss));
    atomicAdd(&w[b * Ss + 2 * k2 + 1], ay * (1.0f / Ss));
}

// u[b,f] += sum_{k in chunk} w[b,k] * x[b,k,f]   (fp32 x for accuracy)
#define KCH 16
__global__ __launch_bounds__(256) void weighted_x(const float* __restrict__ x,
                                                  const float* __restrict__ w,
                                                  float* __restrict__ u)
{
    const int b  = blockIdx.y;
    const int f  = blockIdx.x * 256 + threadIdx.x;
    const int k0 = blockIdx.z * (Ss / KCH);
    const float* xb = x + (size_t)b * Ss * Ee + (size_t)k0 * Ee + f;
    const float* wb = w + b * Ss + k0;
    float acc = 0.0f;
#pragma unroll 4
    for (int k = 0; k < Ss / KCH; k++)
        acc += __ldg(&wb[k]) * xb[(size_t)k * Ee];
    atomicAdd(&u[b * Ee + f], acc);
}

__global__ __launch_bounds__(256) void out_gemm(const float* __restrict__ u,
                                                const float* __restrict__ wv,
                                                const float* __restrict__ bv,
                                                float* __restrict__ out)
{
    const int warp = threadIdx.x >> 5, lane = threadIdx.x & 31;
    const int e = blockIdx.x * 8 + warp;
    const int b = blockIdx.y;
    const float* ub = u + b * Ee;
    const float* wr = wv + (size_t)e * Ee;
    float acc = 0.0f;
    for (int f = lane; f < Ee; f += 32) acc += ub[f] * wr[f];
#pragma unroll
    for (int o = 16; o > 0; o >>= 1) acc += __shfl_down_sync(0xFFFFFFFFu, acc, o);
    if (lane == 0) out[b * Ee + e] = acc + __ldg(&bv[e]);
}

// ---------------------------------------------------------------------------
extern "C" void kernel_launch(void* const* d_in, const int* in_sizes, int n_in,
                              void* d_out, int out_size)
{
    const float* x  = (const float*)d_in[0];
    const float* wq = (const float*)d_in[1];
    const float* bq = (const float*)d_in[2];
    const float* wk = (const float*)d_in[3];
    const float* bk = (const float*)d_in[4];
    const float* wv = (const float*)d_in[5];
    const float* bv = (const float*)d_in[6];
    float* out = (float*)d_out;
    (void)bk;  // constant along k -> cancels in softmax

    __half *xh, *Yh, *E, *Mth;
    float *Mt, *sv, *t3s, *r, *w, *u;
    cudaGetSymbolAddress((void**)&xh,  g_xh);
    cudaGetSymbolAddress((void**)&Yh,  g_Yh);
    cudaGetSymbolAddress((void**)&E,   g_E);
    cudaGetSymbolAddress((void**)&Mt,  g_Mt);
    cudaGetSymbolAddress((void**)&Mth, g_Mth);
    cudaGetSymbolAddress((void**)&sv,  g_sv);
    cudaGetSymbolAddress((void**)&t3s, g_t3s);
    cudaGetSymbolAddress((void**)&r,   g_r);
    cudaGetSymbolAddress((void**)&w,   g_w);
    cudaGetSymbolAddress((void**)&u,   g_u);

    cudaFuncSetAttribute(gemm_f16,
                         cudaFuncAttributeMaxDynamicSharedMemorySize, GEMM_DSMEM);

    const long long SE  = (long long)Ss * Ee;
    const long long SS2 = (long long)Ss * Ss;

    // 1) x -> fp16, fused with zeroing of all accumulators (Mt, sv, r, w, u)
    cvt_x_and_zero<<<(Bb * Ss * Ee / 4 + 255) / 256, 256>>>(
        x, xh, Bb * Ss * Ee / 4, Mt, sv, r, w, u);

    // 2) Mt[f,e] = sum_g Wk[g,f] Wq[g,e]  (split-K 8, atomic), then -> fp16
    {
        dim3 grid(Ee / 128, Ee / 128, MT_SPLITK);
        sgemm_tn_splitk<<<grid, 256>>>(wk, wq, Mt, Ee, Ee, Ee);
    }
    cvt_f32_f16<<<(Ee * Ee / 4 + 255) / 256, 256>>>(Mt, Mth, Ee * Ee / 4);

    // 3) s = Wk^T bq (ECH=64) ; t3s = (xh . s)/32
    {
        dim3 grid(Ee / 256, ECH);
        calc_s<<<grid, 256>>>(wk, bq, sv);
    }
    t3_kernel<<<Bb * Ss / 8, 256>>>(xh, sv, t3s);

    // 4) GEMM1: Yh = xh @ Mth^T   (M=B*S, N=E, K=E)
    {
        dim3 grid(Ee / 128, (Bb * Ss) / 128, 1);
        gemm_f16<<<grid, 128, GEMM_DSMEM>>>(
            xh, Mth, Yh, nullptr, nullptr,
            Bb * Ss, Ee, Ee, 1.0f, 0, 0, 0, 0, 1);
    }

    // 5) GEMM2 + fused softmax-numerator: E[b,q,k] = exp(score-4), r[b,q] = row sums
    {
        dim3 grid(Ss / 128, Ss / 128, Bb);
        gemm_f16<<<grid, 128, GEMM_DSMEM>>>(
            Yh, xh, E, t3s, r,
            Ss, Ss, Ee, 1.0f / 32.0f, SE, SE, SS2, Ss, 2);
    }

    // 6) r -> 1/r ; column means (half2, QCH=16) ; weighted x ; final projection
    inv_r<<<(Bb * Ss + 255) / 256, 256>>>(r, Bb * Ss);
    {
        dim3 grid(Ss / 512, Bb, QCH);
        col_mean<<<grid, 256>>>(E, r, w);
    }
    {
        dim3 grid(Ee / 256, Bb, KCH);
        weighted_x<<<grid, 256>>>(x, w, u);
    }
    {
        dim3 grid(Ee / 8, Bb);
        out_gemm<<<grid, 256>>>(u, wv, bv, out);
    }
}

// round 16
// speedup vs baseline: 1.1693x; 1.0059x over previous
#include <cuda_runtime.h>
#include <cuda_fp16.h>
#include <cstdint>
#include <cstddef>

// Problem constants
#define Bb 16
#define Ss 2048
#define Ee 1024

// ---------------- device scratch (static globals: allocation-free) ----------
__device__ __half g_xh [(size_t)Bb * Ss * Ee];          // 67 MB  x in fp16
__device__ __half g_Yh [(size_t)Bb * Ss * Ee];          // 67 MB  Y = x @ Mt^T
__device__ __half g_E  [(size_t)Bb * Ss * Ss];          // 134 MB exp(score-4)
__device__ float  g_Mt  [(size_t)Ee * Ee];              // 4 MB   Wk^T Wq (fp32)
__device__ __half g_Mth[(size_t)Ee * Ee];               // 2 MB
__device__ float  g_sv [Ee];                            // s = Wk^T bq
__device__ float  g_t3s[Bb * Ss];                       // (x . s)/32
__device__ float  g_r  [Bb * Ss];                       // row sums of E
__device__ float  g_w  [Bb * Ss];                       // softmax col means
__device__ float  g_u  [Bb * Ee];                       // weighted x

// =========================== PTX helpers (base compute_103) =================
__device__ __forceinline__ uint32_t smem_u32(const void* p) {
    uint32_t a;
    asm("{ .reg .u64 t; cvta.to.shared.u64 t, %1; cvt.u32.u64 %0, t; }"
        : "=r"(a) : "l"(p));
    return a;
}
#define CP_ASYNC16(d, s) \
    asm volatile("cp.async.cg.shared.global [%0], [%1], 16;" :: "r"(d), "l"(s))
#define CP_COMMIT() asm volatile("cp.async.commit_group;" ::: "memory")
#define CP_WAIT(n)  asm volatile("cp.async.wait_group %0;" :: "n"(n) : "memory")

// SW64 swizzle for 64-byte rows
#define SWZ64(o) ((o) ^ (((o) >> 3) & 0x30))

__device__ __forceinline__ void ldsm_x4(uint32_t* r, uint32_t addr) {
    asm volatile("ldmatrix.sync.aligned.m8n8.x4.shared.b16 {%0,%1,%2,%3}, [%4];"
                 : "=r"(r[0]), "=r"(r[1]), "=r"(r[2]), "=r"(r[3])
                 : "r"(addr));
}
__device__ __forceinline__ void mma16816(float* c, const uint32_t* a,
                                         const uint32_t* b) {
    asm volatile(
        "mma.sync.aligned.m16n8k16.row.col.f32.f16.f16.f32 "
        "{%0,%1,%2,%3}, {%4,%5,%6,%7}, {%8,%9}, {%0,%1,%2,%3};"
        : "+f"(c[0]), "+f"(c[1]), "+f"(c[2]), "+f"(c[3])
        : "r"(a[0]), "r"(a[1]), "r"(a[2]), "r"(a[3]), "r"(b[0]), "r"(b[1]));
}

// ======================= fp16 NT GEMM via mma.sync ==========================
// Measured-best config (rounds 13/15, 711.8us): CTA tile 128x128x32; 4 warps
// (2x2), warp tile 64x64; 128 threads; __launch_bounds__(128,2) -> 2 CTAs/SM;
// NS=4 stages (65 KB — NS=5's 81 KB broke 2-CTA residency, round 14).
// out_mode 1: Ch[m,n] = fp16( alpha * sum_k A[m,k]*B[n,k] )
// out_mode 2: v = alpha*acc + addv[col]; E = fp16(exp(v-4)); row sums -> rsum.
#define NS 4
#define STAGE 16384              // A 8 KB + B 8 KB
#define GEMM_DSMEM (NS * STAGE + 1024)

__global__ __launch_bounds__(128, 2) void gemm_f16(
    const __half* __restrict__ A, const __half* __restrict__ B,
    __half* __restrict__ C, const float* __restrict__ addv,
    float* __restrict__ rsum,
    int M, int N, int K, float alpha,
    long long sA, long long sB, long long sC, long long sAdd, int out_mode)
{
    extern __shared__ char dynsm[];
    const uint32_t sbase = (smem_u32(dynsm) + 1023u) & ~1023u;

    const int tid  = threadIdx.x;
    const int lane = tid & 31;
    const int wid  = tid >> 5;       // 0..3
    const int wm   = wid >> 1;       // 0..1 -> 64-row band
    const int wn   = wid & 1;        // 0..1 -> 64-col band
    const int NC   = K / 32;

    const size_t arow0 = (size_t)blockIdx.z * sA + (size_t)(blockIdx.y * 128) * K;
    const size_t brow0 = (size_t)blockIdx.z * sB + (size_t)(blockIdx.x * 128) * K;

    auto load_stage = [&](int c) {
        const uint32_t st = sbase + (uint32_t)(c % NS) * STAGE;
        const int kc0 = c * 32;
#pragma unroll
        for (int t = 0; t < 2; t++) {
            const __half* src = t ? B : A;
            const size_t  bs  = t ? brow0 : arow0;
            const uint32_t tb = st + (uint32_t)t * 8192;
#pragma unroll
            for (int i = 0; i < 4; i++) {
                const int idx = tid + 128 * i;      // 0..511
                const int row = idx >> 2;
                const int ch  = idx & 3;
                const __half* g = src + bs + (size_t)row * K + kc0 + ch * 8;
                CP_ASYNC16(tb + SWZ64((uint32_t)(row * 64 + ch * 16)), g);
            }
        }
        CP_COMMIT();
    };

    float acc[4][8][4];
#pragma unroll
    for (int i = 0; i < 4; i++)
#pragma unroll
        for (int j = 0; j < 8; j++)
#pragma unroll
            for (int r = 0; r < 4; r++) acc[i][j][r] = 0.0f;

    load_stage(0);
    load_stage(1);
    load_stage(2);

    const int a_r = wm * 64 + (lane & 7) + ((lane >> 3) & 1) * 8;  // + mi*16
    const int a_c = (lane >> 4) & 1;                               // + ks*2
    const int b_r = wn * 64 + (lane & 7) + ((lane >> 4) & 1) * 8;  // + p*16
    const int b_c = (lane >> 3) & 1;                               // + ks*2

    for (int c = 0; c < NC; c++) {
        CP_WAIT(2);
        __syncthreads();
        if (c + 3 < NC) load_stage(c + 3); else CP_COMMIT();  // keep group count

        const uint32_t st = sbase + (uint32_t)(c % NS) * STAGE;
#pragma unroll
        for (int ks = 0; ks < 2; ks++) {
            uint32_t ah[4][4], bh[8][2];
#pragma unroll
            for (int mi = 0; mi < 4; mi++) {
                const uint32_t off =
                    SWZ64((uint32_t)((a_r + mi * 16) * 64 + (a_c + ks * 2) * 16));
                ldsm_x4(ah[mi], st + off);
            }
#pragma unroll
            for (int p = 0; p < 4; p++) {
                const uint32_t off =
                    SWZ64((uint32_t)((b_r + p * 16) * 64 + (b_c + ks * 2) * 16));
                uint32_t t0[4];
                ldsm_x4(t0, st + 8192 + off);
                bh[2 * p][0] = t0[0]; bh[2 * p][1] = t0[1];
                bh[2 * p + 1][0] = t0[2]; bh[2 * p + 1][1] = t0[3];
            }
#pragma unroll
            for (int mi = 0; mi < 4; mi++)
#pragma unroll
                for (int ni = 0; ni < 8; ni++)
                    mma16816(acc[mi][ni], ah[mi], bh[ni]);
        }
    }

    // ------------------------------ epilogue --------------------------------
    const int gr0 = blockIdx.y * 128 + wm * 64 + (lane >> 2);
    const int gc0 = blockIdx.x * 128 + wn * 64 + 2 * (lane & 3);
    const size_t cb = (size_t)blockIdx.z * sC;

    if (out_mode == 1) {
#pragma unroll
        for (int mi = 0; mi < 4; mi++)
#pragma unroll
            for (int ni = 0; ni < 8; ni++) {
                const int row = gr0 + mi * 16;
                const int col = gc0 + ni * 8;
                *(__half2*)&C[cb + (size_t)row * N + col] =
                    __floats2half2_rn(acc[mi][ni][0] * alpha,
                                      acc[mi][ni][1] * alpha);
                *(__half2*)&C[cb + (size_t)(row + 8) * N + col] =
                    __floats2half2_rn(acc[mi][ni][2] * alpha,
                                      acc[mi][ni][3] * alpha);
            }
    } else {
        const float* av = addv + (size_t)blockIdx.z * sAdd;
        float* rb = rsum + (size_t)blockIdx.z * Ss;
#pragma unroll
        for (int mi = 0; mi < 4; mi++) {
            float s_lo = 0.0f, s_hi = 0.0f;
            const int row = gr0 + mi * 16;
#pragma unroll
            for (int ni = 0; ni < 8; ni++) {
                const int col = gc0 + ni * 8;
                const float a0 = __ldg(&av[col]);
                const float a1 = __ldg(&av[col + 1]);
                const float e0 = __expf(acc[mi][ni][0] * alpha + a0 - 4.0f);
                const float e1 = __expf(acc[mi][ni][1] * alpha + a1 - 4.0f);
                const float e2 = __expf(acc[mi][ni][2] * alpha + a0 - 4.0f);
                const float e3 = __expf(acc[mi][ni][3] * alpha + a1 - 4.0f);
                s_lo += e0 + e1;
                s_hi += e2 + e3;
                *(__half2*)&C[cb + (size_t)row * N + col] =
                    __floats2half2_rn(e0, e1);
                *(__half2*)&C[cb + (size_t)(row + 8) * N + col] =
                    __floats2half2_rn(e2, e3);
            }
            s_lo += __shfl_xor_sync(0xFFFFFFFFu, s_lo, 1);
            s_lo += __shfl_xor_sync(0xFFFFFFFFu, s_lo, 2);
            s_hi += __shfl_xor_sync(0xFFFFFFFFu, s_hi, 1);
            s_hi += __shfl_xor_sync(0xFFFFFFFFu, s_hi, 2);
            if ((lane & 3) == 0) {
                atomicAdd(&rb[row], s_lo);
                atomicAdd(&rb[row + 8], s_hi);
            }
        }
    }
}

// ============= TN fp32 sgemm split-K: Mt[m,n] += sum_g A[g,m]*B[g,n] ========
// MT_SPLITK=8 (rounds 11/13 measured best).
#define MT_SPLITK 8
__global__ __launch_bounds__(256) void sgemm_tn_splitk(
    const float* __restrict__ A, const float* __restrict__ B,
    float* __restrict__ C, int M, int N, int K)
{
    __shared__ float As[8][128];
    __shared__ float Bs[8][128];
    const int tid  = threadIdx.x;
    const int trow = tid >> 4, tcol = tid & 15;
    const int krow = tid >> 5, col4 = (tid & 31) * 4;
    const int m0 = blockIdx.y * 128, n0 = blockIdx.x * 128;
    const int kslice = K / MT_SPLITK;
    const int kbeg = blockIdx.z * kslice, kend = kbeg + kslice;

    float acc[8][8];
#pragma unroll
    for (int i = 0; i < 8; i++)
#pragma unroll
        for (int j = 0; j < 8; j++) acc[i][j] = 0.0f;

    for (int k0 = kbeg; k0 < kend; k0 += 8) {
        const float4 a4 = *(const float4*)&A[(size_t)(k0 + krow) * M + m0 + col4];
        const float4 b4 = *(const float4*)&B[(size_t)(k0 + krow) * N + n0 + col4];
        __syncthreads();
        *(float4*)&As[krow][col4] = a4;
        *(float4*)&Bs[krow][col4] = b4;
        __syncthreads();
#pragma unroll
        for (int kk = 0; kk < 8; kk++) {
            float ra[8], rb[8];
#pragma unroll
            for (int i = 0; i < 8; i++) ra[i] = As[kk][trow * 8 + i];
#pragma unroll
            for (int j = 0; j < 8; j++) rb[j] = Bs[kk][tcol * 8 + j];
#pragma unroll
            for (int i = 0; i < 8; i++)
#pragma unroll
                for (int j = 0; j < 8; j++) acc[i][j] += ra[i] * rb[j];
        }
    }
#pragma unroll
    for (int i = 0; i < 8; i++)
#pragma unroll
        for (int j = 0; j < 8; j++)
            atomicAdd(&C[(size_t)(m0 + trow * 8 + i) * N + n0 + tcol * 8 + j],
                      acc[i][j]);
}

// =============== x -> fp16 conversion fused with accumulator zeroing ========
__global__ __launch_bounds__(256) void cvt_x_and_zero(
    const float* __restrict__ in, __half* __restrict__ out, int n4,
    float* __restrict__ Mt, float* __restrict__ sv,
    float* __restrict__ r, float* __restrict__ w, float* __restrict__ u)
{
    const int idx = blockIdx.x * 256 + threadIdx.x;
    if (idx < n4) {
        const float4 v = ((const float4*)in)[idx];
        ((__half2*)out)[idx * 2 + 0] = __floats2half2_rn(v.x, v.y);
        ((__half2*)out)[idx * 2 + 1] = __floats2half2_rn(v.z, v.w);
    }
    if (idx < Ee * Ee) Mt[idx] = 0.0f;
    if (idx < Ee)      sv[idx] = 0.0f;
    if (idx < Bb * Ss) { r[idx] = 0.0f; w[idx] = 0.0f; }
    if (idx < Bb * Ee) u[idx] = 0.0f;
}

__global__ __launch_bounds__(256) void cvt_f32_f16(
    const float* __restrict__ in, __half* __restrict__ out, int n4)
{
    const int idx = blockIdx.x * 256 + threadIdx.x;
    if (idx >= n4) return;
    const float4 v = ((const float4*)in)[idx];
    ((__half2*)out)[idx * 2 + 0] = __floats2half2_rn(v.x, v.y);
    ((__half2*)out)[idx * 2 + 1] = __floats2half2_rn(v.z, v.w);
}

// s[f] += sum_{e in chunk} Wk[e,f]*bq[e]   grid (Ee/256, ECH); ECH=64 measured.
#define ECH 64
__global__ __launch_bounds__(256) void calc_s(
    const float* __restrict__ Wk, const float* __restrict__ bq,
    float* __restrict__ s)
{
    const int f  = blockIdx.x * 256 + threadIdx.x;
    const int e0 = blockIdx.y * (Ee / ECH);
    float acc = 0.0f;
#pragma unroll 4
    for (int e = e0; e < e0 + Ee / ECH; e++)
        acc += Wk[(size_t)e * Ee + f] * __ldg(&bq[e]);
    atomicAdd(&s[f], acc);
}

// t3s[r] = (xh[r,:] . s) / 32   (warp per row)
__global__ __launch_bounds__(256) void t3_kernel(
    const __half* __restrict__ xh, const float* __restrict__ s,
    float* __restrict__ t3s)
{
    const int warp = threadIdx.x >> 5, lane = threadIdx.x & 31;
    const int row = blockIdx.x * 8 + warp;
    const __half2* xr = (const __half2*)(xh + (size_t)row * Ee);
    float acc = 0.0f;
    for (int e2 = lane; e2 < Ee / 2; e2 += 32) {
        const float2 v = __half22float2(xr[e2]);
        acc += v.x * __ldg(&s[2 * e2]) + v.y * __ldg(&s[2 * e2 + 1]);
    }
#pragma unroll
    for (int o = 16; o > 0; o >>= 1) acc += __shfl_down_sync(0xFFFFFFFFu, acc, o);
    if (lane == 0) t3s[row] = acc * (1.0f / 32.0f);
}

// w[b,2k..2k+1] += (1/S) * sum_{q in chunk} E[b,q,2k..2k+1] / r[b,q]
// 1/r folded in via __fdividef (MUFU, hidden under DRAM stream) — the
// separate inv_r launch is gone.
#define QCH 16
__global__ __launch_bounds__(256) void col_mean(const __half* __restrict__ E,
                                                const float* __restrict__ rs,
                                                float* __restrict__ w)
{
    const int b  = blockIdx.y;
    const int k2 = blockIdx.x * 256 + threadIdx.x;   // half2 index
    const int q0 = blockIdx.z * (Ss / QCH);
    const __half2* base = (const __half2*)(E + (size_t)b * Ss * Ss) + k2;
    const float* rb = rs + b * Ss;
    float ax = 0.0f, ay = 0.0f;
#pragma unroll 4
    for (int q = q0; q < q0 + Ss / QCH; q++) {
        const float2 e = __half22float2(base[(size_t)q * (Ss / 2)]);
        const float rv = __fdividef(1.0f, __ldg(&rb[q]));
        ax += e.x * rv;
        ay += e.y * rv;
    }
    atomicAdd(&w[b * Ss + 2 * k2],     ax * (1.0f / Ss));
    atomicAdd(&w[b * Ss + 2 * k2 + 1], ay * (1.0f / Ss));
}

// u[b,f] += sum_{k in chunk} w[b,k] * xh[b,k,f]
// fp16 x: halves the 268 MB read. Measured in round 5: rel_err 2.3e-5 ->
// 1.9e-4 (quantization-type error, 5x under the 1e-3 threshold).
#define KCH 16
__global__ __launch_bounds__(256) void weighted_x(const __half* __restrict__ xh,
                                                  const float* __restrict__ w,
                                                  float* __restrict__ u)
{
    const int b  = blockIdx.y;
    const int f  = blockIdx.x * 256 + threadIdx.x;
    const int k0 = blockIdx.z * (Ss / KCH);
    const __half* xb = xh + (size_t)b * Ss * Ee + (size_t)k0 * Ee + f;
    const float* wb = w + b * Ss + k0;
    float acc = 0.0f;
#pragma unroll 4
    for (int k = 0; k < Ss / KCH; k++)
        acc += __ldg(&wb[k]) * __half2float(xb[(size_t)k * Ee]);
    atomicAdd(&u[b * Ee + f], acc);
}

__global__ __launch_bounds__(256) void out_gemm(const float* __restrict__ u,
                                                const float* __restrict__ wv,
                                                const float* __restrict__ bv,
                                                float* __restrict__ out)
{
    const int warp = threadIdx.x >> 5, lane = threadIdx.x & 31;
    const int e = blockIdx.x * 8 + warp;
    const int b = blockIdx.y;
    const float* ub = u + b * Ee;
    const float* wr = wv + (size_t)e * Ee;
    float acc = 0.0f;
    for (int f = lane; f < Ee; f += 32) acc += ub[f] * wr[f];
#pragma unroll
    for (int o = 16; o > 0; o >>= 1) acc += __shfl_down_sync(0xFFFFFFFFu, acc, o);
    if (lane == 0) out[b * Ee + e] = acc + __ldg(&bv[e]);
}

// ---------------------------------------------------------------------------
extern "C" void kernel_launch(void* const* d_in, const int* in_sizes, int n_in,
                              void* d_out, int out_size)
{
    const float* x  = (const float*)d_in[0];
    const float* wq = (const float*)d_in[1];
    const float* bq = (const float*)d_in[2];
    const float* wk = (const float*)d_in[3];
    const float* bk = (const float*)d_in[4];
    const float* wv = (const float*)d_in[5];
    const float* bv = (const float*)d_in[6];
    float* out = (float*)d_out;
    (void)bk;  // constant along k -> cancels in softmax

    __half *xh, *Yh, *E, *Mth;
    float *Mt, *sv, *t3s, *r, *w, *u;
    cudaGetSymbolAddress((void**)&xh,  g_xh);
    cudaGetSymbolAddress((void**)&Yh,  g_Yh);
    cudaGetSymbolAddress((void**)&E,   g_E);
    cudaGetSymbolAddress((void**)&Mt,  g_Mt);
    cudaGetSymbolAddress((void**)&Mth, g_Mth);
    cudaGetSymbolAddress((void**)&sv,  g_sv);
    cudaGetSymbolAddress((void**)&t3s, g_t3s);
    cudaGetSymbolAddress((void**)&r,   g_r);
    cudaGetSymbolAddress((void**)&w,   g_w);
    cudaGetSymbolAddress((void**)&u,   g_u);

    cudaFuncSetAttribute(gemm_f16,
                         cudaFuncAttributeMaxDynamicSharedMemorySize, GEMM_DSMEM);

    const long long SE  = (long long)Ss * Ee;
    const long long SS2 = (long long)Ss * Ss;

    // 1) x -> fp16, fused with zeroing of all accumulators (Mt, sv, r, w, u)
    cvt_x_and_zero<<<(Bb * Ss * Ee / 4 + 255) / 256, 256>>>(
        x, xh, Bb * Ss * Ee / 4, Mt, sv, r, w, u);

    // 2) Mt[f,e] = sum_g Wk[g,f] Wq[g,e]  (split-K 8, atomic), then -> fp16
    {
        dim3 grid(Ee / 128, Ee / 128, MT_SPLITK);
        sgemm_tn_splitk<<<grid, 256>>>(wk, wq, Mt, Ee, Ee, Ee);
    }
    cvt_f32_f16<<<(Ee * Ee / 4 + 255) / 256, 256>>>(Mt, Mth, Ee * Ee / 4);

    // 3) s = Wk^T bq (ECH=64) ; t3s = (xh . s)/32
    {
        dim3 grid(Ee / 256, ECH);
        calc_s<<<grid, 256>>>(wk, bq, sv);
    }
    t3_kernel<<<Bb * Ss / 8, 256>>>(xh, sv, t3s);

    // 4) GEMM1: Yh = xh @ Mth^T   (M=B*S, N=E, K=E)
    {
        dim3 grid(Ee / 128, (Bb * Ss) / 128, 1);
        gemm_f16<<<grid, 128, GEMM_DSMEM>>>(
            xh, Mth, Yh, nullptr, nullptr,
            Bb * Ss, Ee, Ee, 1.0f, 0, 0, 0, 0, 1);
    }

    // 5) GEMM2 + fused softmax-numerator: E[b,q,k] = exp(score-4), r[b,q] = row sums
    {
        dim3 grid(Ss / 128, Ss / 128, Bb);
        gemm_f16<<<grid, 128, GEMM_DSMEM>>>(
            Yh, xh, E, t3s, r,
            Ss, Ss, Ee, 1.0f / 32.0f, SE, SE, SS2, Ss, 2);
    }

    // 6) column means (1/r folded in) ; weighted x (fp16) ; final projection
    {
        dim3 grid(Ss / 512, Bb, QCH);
        col_mean<<<grid, 256>>>(E, r, w);
    }
    {
        dim3 grid(Ee / 256, Bb, KCH);
        weighted_x<<<grid, 256>>>(xh, w, u);
    }
    {
        dim3 grid(Ee / 8, Bb);
        out_gemm<<<grid, 256>>>(u, wv, bv, out);
    }
}